// round 9
// baseline (speedup 1.0000x reference)
#include <cuda_runtime.h>

#define NS 20480
#define NSU 10304
#define EMAX 120000
#define TMAX 2097152
#define DHIST 16384
#define NT 512            /* TMAX/4096 lookback tiles */
#define MAXB 160
#define DAMAX 64

__device__ __align__(16) int g_srcHist[NS + 8], g_tgtHist[NS + 8];
__device__ __align__(16) int g_srcBase[NS + 8];
__device__ int g_curA[NS + 8];
__device__ int g_eScat[EMAX], g_ePerm[EMAX];
__device__ int g_tgtS[EMAX];
__device__ __align__(16) int g_prod[NS + 8];
__device__ __align__(16) int g_triSA[TMAX];
__device__ __align__(16) unsigned int g_triSVW[TMAX];
__device__ int g_cA[TMAX];
__device__ unsigned int g_cVW[TMAX];
__device__ __align__(16) int g_histTri[NS + 8];
__device__ int g_triBase[NS + 8];
__device__ __align__(16) int g_deg[NS + 8];
__device__ int g_deg2[NS + 8];
__device__ __align__(16) int g_histD[DHIST + 8];
__device__ int g_cumD[DHIST + 8];
__device__ int g_maxNode, g_P;
__device__ __align__(16) int g_tieEx[NS + 8];
__device__ int g_keep[NS + 8];
__device__ __align__(16) int g_srcPresent[NS + 8], g_present[NS + 8];
__device__ int g_srcRank[NS + 8], g_rank[NS + 8];
__device__ int g_segHead[NS + 8];
__device__ float g_Wt[3 * 64 * 64];
__device__ __align__(16) float g_S[NSU * 128];     // per-u sums: [0:64) B, [64:128) C
__device__ volatile unsigned long long g_tileState[NT + 8];
__device__ volatile int g_arrive[MAXB * 32];
__device__ volatile int g_barPhase;

__device__ __forceinline__ void gridBar(int ep, int nb) {
    __syncthreads();
    if (blockIdx.x == 0) {
        if (threadIdx.x < 32) {
            int lane = threadIdx.x;
            if (lane == 0) { __threadfence(); g_arrive[0] = ep; }
            bool ok;
            do {
                ok = true;
                for (int s = lane; s < nb; s += 32)
                    if (g_arrive[s * 32] < ep) ok = false;
            } while (__ballot_sync(0xffffffffu, !ok));
            if (lane == 0) { __threadfence(); g_barPhase = ep; }
        }
    } else if (threadIdx.x == 0) {
        __threadfence();
        g_arrive[blockIdx.x * 32] = ep;
        while (g_barPhase < ep) __nanosleep(32);
        __threadfence();
    }
    __syncthreads();
}

__device__ __forceinline__ int blockScanEx(int v, int* tot) {
    __shared__ int s_w[32];
    __shared__ int s_tot;
    int lane = threadIdx.x & 31, wid = threadIdx.x >> 5, nw = blockDim.x >> 5;
    int inc = v;
#pragma unroll
    for (int o = 1; o < 32; o <<= 1) {
        int u = __shfl_up_sync(0xffffffffu, inc, o);
        if (lane >= o) inc += u;
    }
    if (lane == 31) s_w[wid] = inc;
    __syncthreads();
    if (wid == 0) {
        int sv2 = (lane < nw) ? s_w[lane] : 0;
        int si = sv2;
#pragma unroll
        for (int o = 1; o < 32; o <<= 1) {
            int u = __shfl_up_sync(0xffffffffu, si, o);
            if (lane >= o) si += u;
        }
        s_w[lane] = si - sv2;
        if (lane == 31) s_tot = si;
    }
    __syncthreads();
    int ex = inc - v + s_w[wid];
    *tot = s_tot;
    __syncthreads();
    return ex;
}

template <int VPT4>
__device__ void sbScanFast(const int* in, int* out, int n) {
    int v[VPT4 * 4];
    const int4* in4 = (const int4*)in;
#pragma unroll
    for (int j = 0; j < VPT4; j++) {
        int4 q = in4[threadIdx.x * VPT4 + j];
        v[4 * j] = q.x; v[4 * j + 1] = q.y; v[4 * j + 2] = q.z; v[4 * j + 3] = q.w;
    }
    int loc = 0;
#pragma unroll
    for (int j = 0; j < VPT4 * 4; j++) { int t = v[j]; v[j] = loc; loc += t; }
    int tot, ex = blockScanEx(loc, &tot);
    int base = threadIdx.x * VPT4 * 4;
#pragma unroll
    for (int j = 0; j < VPT4 * 4; j++) {
        int i = base + j;
        if (i < n) out[i] = ex + v[j];
    }
    if (threadIdx.x == 0) out[n] = tot;
}

__global__ void kBarInit() {
    int i = blockIdx.x * blockDim.x + threadIdx.x;
    if (i < MAXB * 32) g_arrive[i] = 0;
    if (i == 0) g_barPhase = 0;
}

__device__ __forceinline__ void flushSeg(int curA, float2 aB, float2 aC, int lane) {
    int u = g_srcRank[curA];
    float* b0 = g_S + u * 128 + 2 * lane;
    atomicAdd(b0, aB.x);
    atomicAdd(b0 + 1, aB.y);
    atomicAdd(b0 + 64, aC.x);
    atomicAdd(b0 + 65, aC.y);
}

__global__ void __launch_bounds__(1024, 1) kMega(
    const float* __restrict__ x, const int* __restrict__ ei,
    const float* __restrict__ W, const float* __restrict__ bvec,
    float* __restrict__ out, int N, int E)
{
    __shared__ float sv[32][192];
    __shared__ int s_uns[32][DAMAX];
    __shared__ int s_srt[32][DAMAX];
    __shared__ int s_eb[32][DAMAX];
    __shared__ int s_dn[32][DAMAX];
    __shared__ int s_red[32];
    __shared__ int s_dstar, s_r, s_exTile;
    const int tid = threadIdx.x, bid = blockIdx.x, nb = gridDim.x;
    const int gsz = nb * 1024;
    const int g0 = bid * 1024 + tid;
    const int lane = tid & 31, w = tid >> 5;
    const int warpId = g0 >> 5, nwarps = nb * 32;
    const int warpId1 = ((bid - 1) * 1024 + tid) >> 5, nwarps1 = (nb - 1) * 32;
    int ep = 0;

    // ---- ph0: init ----
    for (int i = g0; i < NS; i += gsz) {
        g_srcHist[i] = 0; g_tgtHist[i] = 0; g_histTri[i] = 0; g_deg2[i] = 0;
        g_srcPresent[i] = 0; g_present[i] = 0; g_curA[i] = 0;
    }
    for (int i = g0; i < DHIST; i += gsz) g_histD[i] = 0;
    for (int i = g0; i <= NT; i += gsz) g_tileState[i] = 0ull;
    for (int i = g0; i < NSU * 32; i += gsz)
        ((float4*)g_S)[i] = make_float4(0.f, 0.f, 0.f, 0.f);
    for (int i = g0; i < 12288; i += gsz) {
        int o = i & 63, ii = (i >> 6) & 63, k = i >> 12;
        g_Wt[i] = W[o * 192 + ii * 3 + k];
    }
    if (g0 == 0) g_maxNode = -1;
    gridBar(++ep, nb);

    // ---- ph1: edge histograms ----
    for (int e = g0; e < E; e += gsz) {
        atomicAdd(&g_srcHist[ei[e]], 1);
        atomicAdd(&g_tgtHist[ei[E + e]], 1);
    }
    gridBar(++ep, nb);

    // ---- ph2: b0 scans srcBase ----
    if (bid == 0) sbScanFast<5>(g_srcHist, g_srcBase, N);
    gridBar(++ep, nb);

    // ---- ph3: scatter by src + analytic degree partials ----
    for (int e = g0; e < E; e += gsz) {
        int s = ei[e], t = ei[E + e];
        g_eScat[g_srcBase[s] + atomicAdd(&g_curA[s], 1)] = e;
        atomicAdd(&g_histTri[s], g_srcHist[t]);
        atomicAdd(&g_deg2[t], g_tgtHist[s]);
    }
    gridBar(++ep, nb);

    // ---- ph4: b0: scan triBase.  blocks 1+: deg finalize + maxNode + src sort ----
    if (bid == 0) {
        sbScanFast<5>(g_histTri, g_triBase, N);
    } else {
        int mloc = -1;
        for (int i = (bid - 1) * 1024 + tid; i < NS; i += (nb - 1) * 1024) {
            int d = g_histTri[i] + g_srcHist[i] * g_tgtHist[i] + g_deg2[i];
            g_deg[i] = d;
            if (d > 0 && i > mloc) mloc = i;
        }
#pragma unroll
        for (int o = 16; o; o >>= 1) {
            int u = __shfl_down_sync(0xffffffffu, mloc, o);
            if (u > mloc) mloc = u;
        }
        if (lane == 0) s_red[w] = mloc;
        __syncthreads();
        if (tid < 32) {
            int m = s_red[tid];
#pragma unroll
            for (int o = 16; o; o >>= 1) {
                int u = __shfl_down_sync(0xffffffffu, m, o);
                if (u > m) m = u;
            }
            if (tid == 0 && m >= 0) atomicMax(&g_maxNode, m);
        }
        __syncthreads();
        for (int v = warpId1; v < N; v += nwarps1) {
            int lo = g_srcBase[v], s = g_srcBase[v + 1] - lo;
            for (int i = lane; i < s; i += 32) {
                int val = g_eScat[lo + i], r = 0;
                for (int j = 0; j < s; j++) r += (g_eScat[lo + j] < val);
                g_ePerm[lo + r] = val;
            }
            __syncwarp();
            for (int i = lane; i < s; i += 32)
                g_tgtS[lo + i] = ei[E + g_ePerm[lo + i]];
            __syncwarp();
        }
    }
    gridBar(++ep, nb);

    // ---- ph5: degree histogram ----
    {
        int L = g_maxNode + 1;
        for (int i = g0; i < L; i += gsz) {
            int d = g_deg[i];
            if (d > DHIST - 1) d = DHIST - 1;
            atomicAdd(&g_histD[d], 1);
        }
    }
    gridBar(++ep, nb);

    // ---- ph6: b0: median select + keep.  blocks 1+: direct sorted generation ----
    if (bid == 0) {
        sbScanFast<4>(g_histD, g_cumD, DHIST);
        __syncthreads();
        int L = g_maxNode + 1, half = L >> 1;
        for (int d = tid; d < DHIST; d += 1024)
            if (g_cumD[d] <= half && half < g_cumD[d + 1]) { s_dstar = d; s_r = half - g_cumD[d]; }
        __syncthreads();
        int dstar = s_dstar, r = s_r;
        for (int i = tid; i < NS; i += 1024)
            g_prod[i] = (i < L && g_deg[i] == dstar) ? 1 : 0;
        __syncthreads();
        sbScanFast<5>(g_prod, g_tieEx, N);
        __syncthreads();
        for (int i = tid; i < N; i += 1024) {
            int kp = 1;
            if (i < L) {
                int d = g_deg[i];
                if (d < dstar) kp = 0;
                else if (d == dstar && g_tieEx[i] < r) kp = 0;
            }
            g_keep[i] = kp;
        }
    } else {
        for (int a = warpId1; a < N; a += nwarps1) {
            int lo = g_srcBase[a], da = g_srcBase[a + 1] - lo;
            if (da == 0) continue;
            int dc = da > DAMAX ? DAMAX : da;
            for (int i = lane; i < dc; i += 32) s_uns[w][i] = g_tgtS[lo + i];
            __syncwarp();
            for (int i = lane; i < dc; i += 32) {
                int vi = s_uns[w][i], r = 0;
                for (int j = 0; j < dc; j++) {
                    int vj = s_uns[w][j];
                    r += (vj < vi) | ((vj == vi) & (j < i));
                }
                s_srt[w][r] = vi;
            }
            __syncwarp();
            // preload group bases in parallel (kills dependent-L2 serial loop)
            for (int i = lane; i < dc; i += 32) {
                int v = s_srt[w][i];
                int eb = g_srcBase[v];
                s_eb[w][i] = eb;
                s_dn[w][i] = g_srcBase[v + 1] - eb;
            }
            __syncwarp();
            int p = g_triBase[a];
            int idx = 0;
            while (idx < dc) {
                int v = s_srt[w][idx];
                int k = 1;
                while (idx + k < dc && s_srt[w][idx + k] == v) k++;
                int eb = s_eb[w][idx], din = s_dn[w][idx];
                int tot = k * din;
                unsigned vhi = (unsigned)v << 16;
                for (int j = lane; j < tot; j += 32) {
                    int e = eb + j / k;
                    g_triSA[p + j] = a;
                    g_triSVW[p + j] = vhi | (unsigned)g_tgtS[e];
                }
                p += tot;
                idx += k;
            }
            __syncwarp();
        }
    }
    gridBar(++ep, nb);

    int T = g_triBase[N]; if (T > TMAX) T = TMAX;

    // ---- ph7: single-pass mask + order-preserving compaction + present flags ----
    for (int tile = bid; tile < NT; tile += nb) {
        int t0 = tile * 4096 + tid * 4;
        int4 A = ((const int4*)g_triSA)[t0 >> 2];
        uint4 V = ((const uint4*)g_triSVW)[t0 >> 2];
        int av[4] = {A.x, A.y, A.z, A.w};
        unsigned vv[4] = {V.x, V.y, V.z, V.w};
        int m[4], s = 0;
#pragma unroll
        for (int j = 0; j < 4; j++) {
            m[j] = 0;
            if (t0 + j < T)
                m[j] = g_keep[av[j]] & g_keep[vv[j] >> 16] & g_keep[vv[j] & 0xffffu];
            s += m[j];
        }
        int tot, ex = blockScanEx(s, &tot);
        if (tid == 0) {
            if (tile == 0) {
                g_tileState[0] = (2ull << 32) | (unsigned)tot;
                s_exTile = 0;
            } else {
                g_tileState[tile] = (1ull << 32) | (unsigned)tot;
                int exT = 0, p = tile - 1;
                while (true) {
                    unsigned long long st = g_tileState[p];
                    unsigned f = (unsigned)(st >> 32);
                    if (f == 0) { __nanosleep(32); continue; }
                    exT += (int)(st & 0xffffffffu);
                    if (f == 2) break;
                    p--;
                }
                s_exTile = exT;
                g_tileState[tile] = (2ull << 32) | (unsigned)(exT + tot);
            }
            if (tile == NT - 1) g_P = s_exTile + tot;
        }
        __syncthreads();
        int o = s_exTile + ex;
#pragma unroll
        for (int j = 0; j < 4; j++) {
            if (m[j]) {
                g_cA[o] = av[j]; g_cVW[o] = vv[j]; o++;
                int v = vv[j] >> 16, ww = vv[j] & 0xffffu;
                g_srcPresent[av[j]] = 1;
                g_present[av[j]] = 1; g_present[v] = 1; g_present[ww] = 1;
            }
        }
        __syncthreads();
    }
    gridBar(++ep, nb);

    // ---- ph8: b0: rank scans ----
    if (bid == 0) {
        sbScanFast<5>(g_srcPresent, g_srcRank, N);
        sbScanFast<5>(g_present, g_rank, N);
    }
    gridBar(++ep, nb);

    int P = g_P;
    int U = g_srcRank[N];

    // ---- ph9: new_ei output + segment heads ----
    if (g0 == 0) g_segHead[U] = P;
    for (int p = g0; p < P; p += gsz) {
        int a = g_cA[p];
        unsigned vw = g_cVW[p];
        int base = 64 * U;
        out[base + p]         = (float)g_rank[a];
        out[base + P + p]     = (float)g_rank[vw >> 16];
        out[base + 2 * P + p] = (float)g_rank[vw & 0xffffu];
        if (p == 0 || g_cA[p - 1] != a) g_segHead[g_srcRank[a]] = p;
    }
    gridBar(++ep, nb);

    // ---- ph10: chunk-parallel segment accumulation (atomic partials) ----
    {
        const int CH = 128;
        int nCh = (P + CH - 1) / CH;
        for (int c = warpId; c < nCh; c += nwarps) {
            int p0 = c * CH, p1 = p0 + CH < P ? p0 + CH : P;
            float2 aB = make_float2(0.f, 0.f), aC = make_float2(0.f, 0.f);
            int curA = g_cA[p0];
            int p = p0;
            while (p < p1) {
                int a0 = g_cA[p];
                unsigned vw0 = g_cVW[p];
                bool has1 = (p + 1 < p1);
                int a1 = 0; unsigned vw1 = 0;
                if (has1) { a1 = g_cA[p + 1]; vw1 = g_cVW[p + 1]; }
                float2 b0 = ((const float2*)(x + (vw0 >> 16) * 64))[lane];
                float2 c0 = ((const float2*)(x + (vw0 & 0xffffu) * 64))[lane];
                float2 b1, c1;
                if (has1) {
                    b1 = ((const float2*)(x + (vw1 >> 16) * 64))[lane];
                    c1 = ((const float2*)(x + (vw1 & 0xffffu) * 64))[lane];
                }
                if (a0 != curA) {
                    flushSeg(curA, aB, aC, lane);
                    curA = a0; aB = make_float2(0.f, 0.f); aC = make_float2(0.f, 0.f);
                }
                aB.x += b0.x; aB.y += b0.y; aC.x += c0.x; aC.y += c0.y;
                if (has1) {
                    if (a1 != curA) {
                        flushSeg(curA, aB, aC, lane);
                        curA = a1; aB = make_float2(0.f, 0.f); aC = make_float2(0.f, 0.f);
                    }
                    aB.x += b1.x; aB.y += b1.y; aC.x += c1.x; aC.y += c1.y;
                }
                p += 2;
            }
            flushSeg(curA, aB, aC, lane);
        }
    }
    gridBar(++ep, nb);

    // ---- ph11: per-u finalize: mean + fused 3-tap matvec ----
    for (int u = warpId; u < U; u += nwarps) {
        int h0 = g_segHead[u], h1 = g_segHead[u + 1];
        int a = g_cA[h0];
        float inv = 1.0f / (float)(h1 - h0);
        float2 xa = ((const float2*)(x + a * 64))[lane];
        const float* Su = g_S + u * 128;
        float2 mB = make_float2(Su[2 * lane] * inv, Su[2 * lane + 1] * inv);
        float2 mC = make_float2(Su[64 + 2 * lane] * inv, Su[64 + 2 * lane + 1] * inv);
        sv[w][2 * lane] = xa.x;       sv[w][2 * lane + 1] = xa.y;
        sv[w][64 + 2 * lane] = mB.x;  sv[w][64 + 2 * lane + 1] = mB.y;
        sv[w][128 + 2 * lane] = mC.x; sv[w][128 + 2 * lane + 1] = mC.y;
        __syncwarp();
        float acc0 = bvec[lane], acc1 = bvec[lane + 32];
#pragma unroll 8
        for (int i = 0; i < 64; i++) {
            float v0 = sv[w][i], v1 = sv[w][64 + i], v2 = sv[w][128 + i];
            int base = i * 64 + lane;
            acc0 += g_Wt[base] * v0 + g_Wt[4096 + base] * v1 + g_Wt[8192 + base] * v2;
            acc1 += g_Wt[base + 32] * v0 + g_Wt[4096 + base + 32] * v1 + g_Wt[8192 + base + 32] * v2;
        }
        out[u * 64 + lane] = acc0;
        out[u * 64 + lane + 32] = acc1;
        __syncwarp();
    }
}

extern "C" void kernel_launch(void* const* d_in, const int* in_sizes, int n_in,
                              void* d_out, int out_size) {
    const float* x = (const float*)d_in[0];
    const int* ei = (const int*)d_in[1];
    const float* W = (const float*)d_in[2];
    const float* b = (const float*)d_in[3];
    float* out = (float*)d_out;
    int N = in_sizes[0] / 64;
    int E = in_sizes[1] / 2;

    int dev = 0, sms = 148;
    cudaGetDevice(&dev);
    cudaDeviceGetAttribute(&sms, cudaDevAttrMultiProcessorCount, dev);
    if (sms > MAXB) sms = MAXB;

    kBarInit<<<20, 256>>>();
    kMega<<<sms, 1024>>>(x, ei, W, b, out, N, E);
}

// round 10
// speedup vs baseline: 1.1804x; 1.1804x over previous
#include <cuda_runtime.h>

#define NS 20480
#define EMAX 120000
#define TMAX 2097152
#define DHIST 16384
#define NT 512            /* TMAX/4096 lookback tiles */
#define MAXB 160
#define DAMAX 64

__device__ __align__(16) int g_srcHist[NS + 8], g_tgtHist[NS + 8];
__device__ __align__(16) int g_srcBase[NS + 8];
__device__ int g_curA[NS + 8];
__device__ int g_eScat[EMAX], g_ePerm[EMAX];
__device__ int g_tgtS[EMAX];
__device__ __align__(16) int g_prod[NS + 8];
__device__ __align__(16) int g_triSA[TMAX];
__device__ __align__(16) unsigned int g_triSVW[TMAX];
__device__ int g_cA[TMAX];
__device__ unsigned int g_cVW[TMAX];
__device__ __align__(16) int g_histTri[NS + 8];
__device__ int g_triBase[NS + 8];
__device__ __align__(16) int g_deg[NS + 8];
__device__ int g_deg2[NS + 8];
__device__ __align__(16) int g_histD[DHIST + 8];
__device__ int g_cumD[DHIST + 8];
__device__ int g_maxNode, g_P;
__device__ __align__(16) int g_tieEx[NS + 8];
__device__ int g_keep[NS + 8];
__device__ __align__(16) int g_srcPresent[NS + 8], g_present[NS + 8];
__device__ int g_srcRank[NS + 8], g_rank[NS + 8];
__device__ int g_segHead[NS + 8];
__device__ float g_Wt[3 * 64 * 64];
__device__ volatile unsigned long long g_tileState[NT + 8];
__device__ volatile int g_arrive[MAXB * 32];
__device__ volatile int g_barPhase;

__device__ __forceinline__ void gridBar(int ep, int nb) {
    __syncthreads();
    if (blockIdx.x == 0) {
        if (threadIdx.x < 32) {
            int lane = threadIdx.x;
            if (lane == 0) { __threadfence(); g_arrive[0] = ep; }
            bool ok;
            do {
                ok = true;
                for (int s = lane; s < nb; s += 32)
                    if (g_arrive[s * 32] < ep) ok = false;
            } while (__ballot_sync(0xffffffffu, !ok));
            if (lane == 0) { __threadfence(); g_barPhase = ep; }
        }
    } else if (threadIdx.x == 0) {
        __threadfence();
        g_arrive[blockIdx.x * 32] = ep;
        while (g_barPhase < ep) __nanosleep(32);
        __threadfence();
    }
    __syncthreads();
}

__device__ __forceinline__ int blockScanEx(int v, int* tot) {
    __shared__ int s_w[32];
    __shared__ int s_tot;
    int lane = threadIdx.x & 31, wid = threadIdx.x >> 5, nw = blockDim.x >> 5;
    int inc = v;
#pragma unroll
    for (int o = 1; o < 32; o <<= 1) {
        int u = __shfl_up_sync(0xffffffffu, inc, o);
        if (lane >= o) inc += u;
    }
    if (lane == 31) s_w[wid] = inc;
    __syncthreads();
    if (wid == 0) {
        int sv2 = (lane < nw) ? s_w[lane] : 0;
        int si = sv2;
#pragma unroll
        for (int o = 1; o < 32; o <<= 1) {
            int u = __shfl_up_sync(0xffffffffu, si, o);
            if (lane >= o) si += u;
        }
        s_w[lane] = si - sv2;
        if (lane == 31) s_tot = si;
    }
    __syncthreads();
    int ex = inc - v + s_w[wid];
    *tot = s_tot;
    __syncthreads();
    return ex;
}

template <int VPT4>
__device__ void sbScanFast(const int* in, int* out, int n) {
    int v[VPT4 * 4];
    const int4* in4 = (const int4*)in;
#pragma unroll
    for (int j = 0; j < VPT4; j++) {
        int4 q = in4[threadIdx.x * VPT4 + j];
        v[4 * j] = q.x; v[4 * j + 1] = q.y; v[4 * j + 2] = q.z; v[4 * j + 3] = q.w;
    }
    int loc = 0;
#pragma unroll
    for (int j = 0; j < VPT4 * 4; j++) { int t = v[j]; v[j] = loc; loc += t; }
    int tot, ex = blockScanEx(loc, &tot);
    int base = threadIdx.x * VPT4 * 4;
#pragma unroll
    for (int j = 0; j < VPT4 * 4; j++) {
        int i = base + j;
        if (i < n) out[i] = ex + v[j];
    }
    if (threadIdx.x == 0) out[n] = tot;
}

__global__ void kBarInit() {
    int i = blockIdx.x * blockDim.x + threadIdx.x;
    if (i < MAXB * 32) g_arrive[i] = 0;
    if (i == 0) g_barPhase = 0;
}

__global__ void __launch_bounds__(1024, 1) kMega(
    const float* __restrict__ x, const int* __restrict__ ei,
    const float* __restrict__ W, const float* __restrict__ bvec,
    float* __restrict__ out, int N, int E)
{
    __shared__ float sv[32][192];
    __shared__ int s_uns[32][DAMAX];
    __shared__ int s_srt[32][DAMAX];
    __shared__ int s_eb[32][DAMAX];
    __shared__ int s_dn[32][DAMAX];
    __shared__ int s_red[32];
    __shared__ int s_dstar, s_r, s_exTile;
    const int tid = threadIdx.x, bid = blockIdx.x, nb = gridDim.x;
    const int gsz = nb * 1024;
    const int g0 = bid * 1024 + tid;
    const int lane = tid & 31, w = tid >> 5;
    const int warpId = g0 >> 5, nwarps = nb * 32;
    const int warpId1 = ((bid - 1) * 1024 + tid) >> 5, nwarps1 = (nb - 1) * 32;
    int ep = 0;

    // ---- ph0: init ----
    for (int i = g0; i < NS; i += gsz) {
        g_srcHist[i] = 0; g_tgtHist[i] = 0; g_histTri[i] = 0; g_deg2[i] = 0;
        g_srcPresent[i] = 0; g_present[i] = 0; g_curA[i] = 0;
    }
    for (int i = g0; i < DHIST; i += gsz) g_histD[i] = 0;
    for (int i = g0; i <= NT; i += gsz) g_tileState[i] = 0ull;
    for (int i = g0; i < 12288; i += gsz) {
        int o = i & 63, ii = (i >> 6) & 63, k = i >> 12;
        g_Wt[i] = W[o * 192 + ii * 3 + k];
    }
    if (g0 == 0) g_maxNode = -1;
    gridBar(++ep, nb);

    // ---- ph1: edge histograms ----
    for (int e = g0; e < E; e += gsz) {
        atomicAdd(&g_srcHist[ei[e]], 1);
        atomicAdd(&g_tgtHist[ei[E + e]], 1);
    }
    gridBar(++ep, nb);

    // ---- ph2: b0 scans srcBase ----
    if (bid == 0) sbScanFast<5>(g_srcHist, g_srcBase, N);
    gridBar(++ep, nb);

    // ---- ph3: scatter by src + analytic degree partials ----
    for (int e = g0; e < E; e += gsz) {
        int s = ei[e], t = ei[E + e];
        g_eScat[g_srcBase[s] + atomicAdd(&g_curA[s], 1)] = e;
        atomicAdd(&g_histTri[s], g_srcHist[t]);
        atomicAdd(&g_deg2[t], g_tgtHist[s]);
    }
    gridBar(++ep, nb);

    // ---- ph4: b0: scan triBase.  blocks 1+: deg finalize + maxNode + src sort ----
    if (bid == 0) {
        sbScanFast<5>(g_histTri, g_triBase, N);
    } else {
        int mloc = -1;
        for (int i = (bid - 1) * 1024 + tid; i < NS; i += (nb - 1) * 1024) {
            int d = g_histTri[i] + g_srcHist[i] * g_tgtHist[i] + g_deg2[i];
            g_deg[i] = d;
            if (d > 0 && i > mloc) mloc = i;
        }
#pragma unroll
        for (int o = 16; o; o >>= 1) {
            int u = __shfl_down_sync(0xffffffffu, mloc, o);
            if (u > mloc) mloc = u;
        }
        if (lane == 0) s_red[w] = mloc;
        __syncthreads();
        if (tid < 32) {
            int m = s_red[tid];
#pragma unroll
            for (int o = 16; o; o >>= 1) {
                int u = __shfl_down_sync(0xffffffffu, m, o);
                if (u > m) m = u;
            }
            if (tid == 0 && m >= 0) atomicMax(&g_maxNode, m);
        }
        __syncthreads();
        for (int v = warpId1; v < N; v += nwarps1) {
            int lo = g_srcBase[v], s = g_srcBase[v + 1] - lo;
            for (int i = lane; i < s; i += 32) {
                int val = g_eScat[lo + i], r = 0;
                for (int j = 0; j < s; j++) r += (g_eScat[lo + j] < val);
                g_ePerm[lo + r] = val;
            }
            __syncwarp();
            for (int i = lane; i < s; i += 32)
                g_tgtS[lo + i] = ei[E + g_ePerm[lo + i]];
            __syncwarp();
        }
    }
    gridBar(++ep, nb);

    // ---- ph5: degree histogram ----
    {
        int L = g_maxNode + 1;
        for (int i = g0; i < L; i += gsz) {
            int d = g_deg[i];
            if (d > DHIST - 1) d = DHIST - 1;
            atomicAdd(&g_histD[d], 1);
        }
    }
    gridBar(++ep, nb);

    // ---- ph6: b0: median select + keep.  blocks 1+: direct sorted generation ----
    if (bid == 0) {
        sbScanFast<4>(g_histD, g_cumD, DHIST);
        __syncthreads();
        int L = g_maxNode + 1, half = L >> 1;
        for (int d = tid; d < DHIST; d += 1024)
            if (g_cumD[d] <= half && half < g_cumD[d + 1]) { s_dstar = d; s_r = half - g_cumD[d]; }
        __syncthreads();
        int dstar = s_dstar, r = s_r;
        for (int i = tid; i < NS; i += 1024)
            g_prod[i] = (i < L && g_deg[i] == dstar) ? 1 : 0;
        __syncthreads();
        sbScanFast<5>(g_prod, g_tieEx, N);
        __syncthreads();
        for (int i = tid; i < N; i += 1024) {
            int kp = 1;
            if (i < L) {
                int d = g_deg[i];
                if (d < dstar) kp = 0;
                else if (d == dstar && g_tieEx[i] < r) kp = 0;
            }
            g_keep[i] = kp;
        }
    } else {
        for (int a = warpId1; a < N; a += nwarps1) {
            int lo = g_srcBase[a], da = g_srcBase[a + 1] - lo;
            if (da == 0) continue;
            int dc = da > DAMAX ? DAMAX : da;
            for (int i = lane; i < dc; i += 32) s_uns[w][i] = g_tgtS[lo + i];
            __syncwarp();
            for (int i = lane; i < dc; i += 32) {
                int vi = s_uns[w][i], r = 0;
                for (int j = 0; j < dc; j++) {
                    int vj = s_uns[w][j];
                    r += (vj < vi) | ((vj == vi) & (j < i));
                }
                s_srt[w][r] = vi;
            }
            __syncwarp();
            for (int i = lane; i < dc; i += 32) {
                int v = s_srt[w][i];
                int eb = g_srcBase[v];
                s_eb[w][i] = eb;
                s_dn[w][i] = g_srcBase[v + 1] - eb;
            }
            __syncwarp();
            int p = g_triBase[a];
            int idx = 0;
            while (idx < dc) {
                int v = s_srt[w][idx];
                int k = 1;
                while (idx + k < dc && s_srt[w][idx + k] == v) k++;
                int eb = s_eb[w][idx], din = s_dn[w][idx];
                int tot = k * din;
                unsigned vhi = (unsigned)v << 16;
                for (int j = lane; j < tot; j += 32) {
                    int e = eb + j / k;
                    g_triSA[p + j] = a;
                    g_triSVW[p + j] = vhi | (unsigned)g_tgtS[e];
                }
                p += tot;
                idx += k;
            }
            __syncwarp();
        }
    }
    gridBar(++ep, nb);

    int T = g_triBase[N]; if (T > TMAX) T = TMAX;

    // ---- ph7: single-pass mask + order-preserving compaction + present flags ----
    for (int tile = bid; tile < NT; tile += nb) {
        int t0 = tile * 4096 + tid * 4;
        int4 A = ((const int4*)g_triSA)[t0 >> 2];
        uint4 V = ((const uint4*)g_triSVW)[t0 >> 2];
        int av[4] = {A.x, A.y, A.z, A.w};
        unsigned vv[4] = {V.x, V.y, V.z, V.w};
        int m[4], s = 0;
#pragma unroll
        for (int j = 0; j < 4; j++) {
            m[j] = 0;
            if (t0 + j < T)
                m[j] = g_keep[av[j]] & g_keep[vv[j] >> 16] & g_keep[vv[j] & 0xffffu];
            s += m[j];
        }
        int tot, ex = blockScanEx(s, &tot);
        if (tid == 0) {
            if (tile == 0) {
                g_tileState[0] = (2ull << 32) | (unsigned)tot;
                s_exTile = 0;
            } else {
                g_tileState[tile] = (1ull << 32) | (unsigned)tot;
                int exT = 0, p = tile - 1;
                while (true) {
                    unsigned long long st = g_tileState[p];
                    unsigned f = (unsigned)(st >> 32);
                    if (f == 0) { __nanosleep(32); continue; }
                    exT += (int)(st & 0xffffffffu);
                    if (f == 2) break;
                    p--;
                }
                s_exTile = exT;
                g_tileState[tile] = (2ull << 32) | (unsigned)(exT + tot);
            }
            if (tile == NT - 1) g_P = s_exTile + tot;
        }
        __syncthreads();
        int o = s_exTile + ex;
#pragma unroll
        for (int j = 0; j < 4; j++) {
            if (m[j]) {
                g_cA[o] = av[j]; g_cVW[o] = vv[j]; o++;
                int v = vv[j] >> 16, ww = vv[j] & 0xffffu;
                g_srcPresent[av[j]] = 1;
                g_present[av[j]] = 1; g_present[v] = 1; g_present[ww] = 1;
            }
        }
        __syncthreads();
    }
    gridBar(++ep, nb);

    // ---- ph8: rank scans on TWO blocks in parallel ----
    if (bid == 0) sbScanFast<5>(g_srcPresent, g_srcRank, N);
    else if (bid == 1) sbScanFast<5>(g_present, g_rank, N);
    gridBar(++ep, nb);

    int P = g_P;
    int U = g_srcRank[N];

    // ---- ph9: new_ei output + segment heads ----
    if (g0 == 0) g_segHead[U] = P;
    for (int p = g0; p < P; p += gsz) {
        int a = g_cA[p];
        unsigned vw = g_cVW[p];
        int base = 64 * U;
        out[base + p]         = (float)g_rank[a];
        out[base + P + p]     = (float)g_rank[vw >> 16];
        out[base + 2 * P + p] = (float)g_rank[vw & 0xffffu];
        if (p == 0 || g_cA[p - 1] != a) g_segHead[g_srcRank[a]] = p;
    }
    gridBar(++ep, nb);

    // ---- ph10: segment-mean (batched MLP gathers) + fused 3-tap matvec ----
    for (int u = warpId; u < U; u += nwarps) {
        int h0 = g_segHead[u], h1 = g_segHead[u + 1];
        int a = g_cA[h0];
        float2 aB = make_float2(0.f, 0.f), aC = make_float2(0.f, 0.f);
        for (int p0 = h0; p0 < h1; p0 += 32) {
            int rem = h1 - p0; if (rem > 32) rem = 32;
            unsigned vwl = 0;
            if (lane < rem) vwl = g_cVW[p0 + lane];   // coalesced descriptor batch
#pragma unroll 8
            for (int j = 0; j < rem; j++) {
                unsigned vw = __shfl_sync(0xffffffffu, vwl, j);
                float2 bb = ((const float2*)(x + (vw >> 16) * 64))[lane];
                float2 cc = ((const float2*)(x + (vw & 0xffffu) * 64))[lane];
                aB.x += bb.x; aB.y += bb.y;
                aC.x += cc.x; aC.y += cc.y;
            }
        }
        float inv = 1.0f / (float)(h1 - h0);
        float2 xa = ((const float2*)(x + a * 64))[lane];
        sv[w][2 * lane] = xa.x;              sv[w][2 * lane + 1] = xa.y;
        sv[w][64 + 2 * lane] = aB.x * inv;   sv[w][64 + 2 * lane + 1] = aB.y * inv;
        sv[w][128 + 2 * lane] = aC.x * inv;  sv[w][128 + 2 * lane + 1] = aC.y * inv;
        __syncwarp();
        float acc0 = bvec[lane], acc1 = bvec[lane + 32];
#pragma unroll 8
        for (int i = 0; i < 64; i++) {
            float v0 = sv[w][i], v1 = sv[w][64 + i], v2 = sv[w][128 + i];
            int base = i * 64 + lane;
            acc0 += g_Wt[base] * v0 + g_Wt[4096 + base] * v1 + g_Wt[8192 + base] * v2;
            acc1 += g_Wt[base + 32] * v0 + g_Wt[4096 + base + 32] * v1 + g_Wt[8192 + base + 32] * v2;
        }
        out[u * 64 + lane] = acc0;
        out[u * 64 + lane + 32] = acc1;
        __syncwarp();
    }
}

extern "C" void kernel_launch(void* const* d_in, const int* in_sizes, int n_in,
                              void* d_out, int out_size) {
    const float* x = (const float*)d_in[0];
    const int* ei = (const int*)d_in[1];
    const float* W = (const float*)d_in[2];
    const float* b = (const float*)d_in[3];
    float* out = (float*)d_out;
    int N = in_sizes[0] / 64;
    int E = in_sizes[1] / 2;

    int dev = 0, sms = 148;
    cudaGetDevice(&dev);
    cudaDeviceGetAttribute(&sms, cudaDevAttrMultiProcessorCount, dev);
    if (sms > MAXB) sms = MAXB;

    kBarInit<<<20, 256>>>();
    kMega<<<sms, 1024>>>(x, ei, W, b, out, N, E);
}